// round 1
// baseline (speedup 1.0000x reference)
#include <cuda_runtime.h>
#include <math.h>

#define B_ 16
#define C_ 512
#define HW_ 4096
#define HEADS_ 8
#define HK_ 64

// Scratch (device globals: allocation-free per harness rules)
__device__ float g_q[B_ * C_ * HW_];
__device__ float g_k[B_ * C_ * HW_];     // reused for AV after ctx is built
__device__ float g_v[B_ * C_ * HW_];
__device__ float g_ctx[B_ * HEADS_ * HK_ * HK_];

// ---------------------------------------------------------------------------
// Generic projection GEMM:  Y[b,o,l] = sum_i W[o,i] * X[b,i,l] + bias[o]
// W: [512,512] row-major.  Block tile 64x64, BK=16, 256 threads, 4x4/thread.
// ---------------------------------------------------------------------------
__global__ void __launch_bounds__(256) proj_gemm(
    const float* __restrict__ W, const float* __restrict__ bias,
    const float* __restrict__ X, float* __restrict__ Y)
{
    __shared__ float Ws[16][64];   // [k][m]
    __shared__ float Xs[16][64];   // [k][n]
    const int b  = blockIdx.z;
    const int n0 = blockIdx.x * 64;
    const int m0 = blockIdx.y * 64;
    const float* Xb = X + (size_t)b * C_ * HW_;
    float*       Yb = Y + (size_t)b * C_ * HW_;
    const int tid = threadIdx.x;
    const int tx = tid & 15, ty = tid >> 4;

    float acc[4][4] = {};
    for (int k0 = 0; k0 < C_; k0 += 16) {
        {   // W tile 64(m) x 16(k), transposed into Ws[k][m]
            int mm = tid >> 2;
            int ks = (tid & 3) << 2;
            float4 w4 = *(const float4*)(W + (size_t)(m0 + mm) * C_ + k0 + ks);
            Ws[ks + 0][mm] = w4.x; Ws[ks + 1][mm] = w4.y;
            Ws[ks + 2][mm] = w4.z; Ws[ks + 3][mm] = w4.w;
        }
        {   // X tile 16(k) x 64(n)
            int ii = tid >> 4;
            int ls = (tid & 15) << 2;
            *(float4*)&Xs[ii][ls] =
                *(const float4*)(Xb + (size_t)(k0 + ii) * HW_ + n0 + ls);
        }
        __syncthreads();
        #pragma unroll
        for (int kk = 0; kk < 16; kk++) {
            float4 a4 = *(float4*)&Ws[kk][ty << 2];
            float4 b4 = *(float4*)&Xs[kk][tx << 2];
            float a[4] = {a4.x, a4.y, a4.z, a4.w};
            float c[4] = {b4.x, b4.y, b4.z, b4.w};
            #pragma unroll
            for (int i = 0; i < 4; i++)
                #pragma unroll
                for (int j = 0; j < 4; j++)
                    acc[i][j] += a[i] * c[j];
        }
        __syncthreads();
    }
    #pragma unroll
    for (int i = 0; i < 4; i++) {
        float bi = bias[m0 + (ty << 2) + i];
        float4 o4 = make_float4(acc[i][0] + bi, acc[i][1] + bi,
                                acc[i][2] + bi, acc[i][3] + bi);
        *(float4*)(Yb + (size_t)(m0 + (ty << 2) + i) * HW_ + n0 + (tx << 2)) = o4;
    }
}

// ---------------------------------------------------------------------------
// Softmax over the spatial axis (rows of length 4096). In-place. One block/row.
// ---------------------------------------------------------------------------
__global__ void __launch_bounds__(256) softmax_spatial(float* __restrict__ data)
{
    __shared__ float buf[HW_];
    __shared__ float red[8];
    __shared__ float bcast;
    float* p = data + (size_t)blockIdx.x * HW_;
    const int tid = threadIdx.x;

    float mx = -1e30f;
    #pragma unroll
    for (int r = 0; r < 4; r++) {
        int idx = (tid << 2) + r * 1024;
        float4 v = *(const float4*)(p + idx);
        *(float4*)&buf[idx] = v;
        mx = fmaxf(mx, fmaxf(fmaxf(v.x, v.y), fmaxf(v.z, v.w)));
    }
    #pragma unroll
    for (int o = 16; o > 0; o >>= 1) mx = fmaxf(mx, __shfl_xor_sync(~0u, mx, o));
    if ((tid & 31) == 0) red[tid >> 5] = mx;
    __syncthreads();
    if (tid == 0) {
        float m = red[0];
        #pragma unroll
        for (int i = 1; i < 8; i++) m = fmaxf(m, red[i]);
        bcast = m;
    }
    __syncthreads();
    mx = bcast;

    float s = 0.f;
    #pragma unroll
    for (int r = 0; r < 4; r++) {
        int idx = (tid << 2) + r * 1024;
        float4 v = *(float4*)&buf[idx];
        v.x = expf(v.x - mx); v.y = expf(v.y - mx);
        v.z = expf(v.z - mx); v.w = expf(v.w - mx);
        *(float4*)&buf[idx] = v;
        s += v.x + v.y + v.z + v.w;
    }
    #pragma unroll
    for (int o = 16; o > 0; o >>= 1) s += __shfl_xor_sync(~0u, s, o);
    if ((tid & 31) == 0) red[tid >> 5] = s;
    __syncthreads();
    if (tid == 0) {
        float m = 0.f;
        #pragma unroll
        for (int i = 0; i < 8; i++) m += red[i];
        bcast = 1.0f / m;
    }
    __syncthreads();
    const float inv = bcast;
    #pragma unroll
    for (int r = 0; r < 4; r++) {
        int idx = (tid << 2) + r * 1024;
        float4 v = *(float4*)&buf[idx];
        v.x *= inv; v.y *= inv; v.z *= inv; v.w *= inv;
        *(float4*)(p + idx) = v;
    }
}

// ---------------------------------------------------------------------------
// Softmax over the 64-channel (per-head) axis for Q. One thread per (b,h,l).
// ---------------------------------------------------------------------------
__global__ void __launch_bounds__(256) softmax_channel(float* __restrict__ q)
{
    const size_t t = (size_t)blockIdx.x * 256 + threadIdx.x;   // < B*HEADS*HW
    const int l  = (int)(t & (HW_ - 1));
    const int bh = (int)(t >> 12);
    float* base = q + (size_t)bh * HK_ * HW_ + l;

    float r[64];
    float mx = -1e30f;
    #pragma unroll
    for (int k = 0; k < 64; k++) { r[k] = base[(size_t)k * HW_]; mx = fmaxf(mx, r[k]); }
    float s = 0.f;
    #pragma unroll
    for (int k = 0; k < 64; k++) { r[k] = expf(r[k] - mx); s += r[k]; }
    const float inv = 1.0f / s;
    #pragma unroll
    for (int k = 0; k < 64; k++) base[(size_t)k * HW_] = r[k] * inv;
}

// ---------------------------------------------------------------------------
// ctx[b,h,k,v] = sum_l K[b,h,k,l] * V[b,h,v,l].  One block per (b,h).
// ---------------------------------------------------------------------------
__global__ void __launch_bounds__(256) ctx_gemm(
    const float* __restrict__ K, const float* __restrict__ V,
    float* __restrict__ C)
{
    __shared__ float Ks[64][33];
    __shared__ float Vs[64][33];
    const int bh = blockIdx.x;
    const float* Kp = K + (size_t)bh * HK_ * HW_;
    const float* Vp = V + (size_t)bh * HK_ * HW_;
    const int tid = threadIdx.x;
    const int tx = tid & 15, ty = tid >> 4;

    float acc[4][4] = {};
    for (int l0 = 0; l0 < HW_; l0 += 32) {
        #pragma unroll
        for (int rp = 0; rp < 2; rp++) {
            int idx = tid + rp * 256;       // 0..511
            int row = idx >> 3;             // 0..63
            int ls  = (idx & 7) << 2;       // 0..28
            float4 k4 = *(const float4*)(Kp + (size_t)row * HW_ + l0 + ls);
            Ks[row][ls + 0] = k4.x; Ks[row][ls + 1] = k4.y;
            Ks[row][ls + 2] = k4.z; Ks[row][ls + 3] = k4.w;
            float4 v4 = *(const float4*)(Vp + (size_t)row * HW_ + l0 + ls);
            Vs[row][ls + 0] = v4.x; Vs[row][ls + 1] = v4.y;
            Vs[row][ls + 2] = v4.z; Vs[row][ls + 3] = v4.w;
        }
        __syncthreads();
        #pragma unroll
        for (int ll = 0; ll < 32; ll++) {
            float a[4], c[4];
            #pragma unroll
            for (int i = 0; i < 4; i++) { a[i] = Ks[(ty << 2) + i][ll]; c[i] = Vs[(tx << 2) + i][ll]; }
            #pragma unroll
            for (int i = 0; i < 4; i++)
                #pragma unroll
                for (int j = 0; j < 4; j++)
                    acc[i][j] += a[i] * c[j];
        }
        __syncthreads();
    }
    float* Cp = C + (size_t)bh * HK_ * HK_;
    #pragma unroll
    for (int i = 0; i < 4; i++) {
        float4 o4 = make_float4(acc[i][0], acc[i][1], acc[i][2], acc[i][3]);
        *(float4*)(Cp + (size_t)((ty << 2) + i) * 64 + (tx << 2)) = o4;
    }
}

// ---------------------------------------------------------------------------
// av[b,h,v,l] = sum_k ctx[b,h,k,v] * q[b,h,k,l].
// Grid: (HW/64, B*HEADS). ctx resident in smem.
// ---------------------------------------------------------------------------
__global__ void __launch_bounds__(256) av_gemm(
    const float* __restrict__ C, const float* __restrict__ Q,
    float* __restrict__ AV)
{
    __shared__ float Cs[64][64];   // [k][v]
    __shared__ float Qs[16][64];   // [k][l]
    const int bh = blockIdx.y;
    const int n0 = blockIdx.x * 64;
    const float* Cp = C  + (size_t)bh * HK_ * HK_;
    const float* Qp = Q  + (size_t)bh * HK_ * HW_;
    float*       Ap = AV + (size_t)bh * HK_ * HW_;
    const int tid = threadIdx.x;
    const int tx = tid & 15, ty = tid >> 4;

    #pragma unroll
    for (int rr = 0; rr < 4; rr++)
        ((float4*)Cs)[tid + rr * 256] = ((const float4*)Cp)[tid + rr * 256];

    float acc[4][4] = {};
    for (int k0 = 0; k0 < 64; k0 += 16) {
        int ii = tid >> 4, ls = (tid & 15) << 2;
        *(float4*)&Qs[ii][ls] =
            *(const float4*)(Qp + (size_t)(k0 + ii) * HW_ + n0 + ls);
        __syncthreads();
        #pragma unroll
        for (int kk = 0; kk < 16; kk++) {
            float4 a4 = *(float4*)&Cs[k0 + kk][ty << 2];   // ctx[k][v0..v0+3]
            float4 b4 = *(float4*)&Qs[kk][tx << 2];
            float a[4] = {a4.x, a4.y, a4.z, a4.w};
            float c[4] = {b4.x, b4.y, b4.z, b4.w};
            #pragma unroll
            for (int i = 0; i < 4; i++)
                #pragma unroll
                for (int j = 0; j < 4; j++)
                    acc[i][j] += a[i] * c[j];
        }
        __syncthreads();
    }
    #pragma unroll
    for (int i = 0; i < 4; i++) {
        float4 o4 = make_float4(acc[i][0], acc[i][1], acc[i][2], acc[i][3]);
        *(float4*)(Ap + (size_t)((ty << 2) + i) * HW_ + n0 + (tx << 2)) = o4;
    }
}

// ---------------------------------------------------------------------------
extern "C" void kernel_launch(void* const* d_in, const int* in_sizes, int n_in,
                              void* d_out, int out_size)
{
    const float* x  = (const float*)d_in[0];
    const float* Wk = (const float*)d_in[1];
    const float* bk = (const float*)d_in[2];
    const float* Wq = (const float*)d_in[3];
    const float* bq = (const float*)d_in[4];
    const float* Wv = (const float*)d_in[5];
    const float* bv = (const float*)d_in[6];
    const float* Wr = (const float*)d_in[7];
    const float* br = (const float*)d_in[8];
    float* out = (float*)d_out;

    float *q, *k, *v, *ctx;
    cudaGetSymbolAddress((void**)&q,   g_q);
    cudaGetSymbolAddress((void**)&k,   g_k);
    cudaGetSymbolAddress((void**)&v,   g_v);
    cudaGetSymbolAddress((void**)&ctx, g_ctx);

    dim3 pg(HW_ / 64, C_ / 64, B_);
    proj_gemm<<<pg, 256>>>(Wq, bq, x, q);
    proj_gemm<<<pg, 256>>>(Wk, bk, x, k);
    proj_gemm<<<pg, 256>>>(Wv, bv, x, v);

    softmax_spatial<<<B_ * C_, 256>>>(k);
    softmax_channel<<<(B_ * HEADS_ * HW_) / 256, 256>>>(q);

    ctx_gemm<<<B_ * HEADS_, 256>>>(k, v, ctx);
    av_gemm<<<dim3(HW_ / 64, B_ * HEADS_), 256>>>(ctx, q, k);  // AV into g_k

    proj_gemm<<<pg, 256>>>(Wr, br, k, out);
}

// round 3
// speedup vs baseline: 4.2795x; 4.2795x over previous
#include <cuda_runtime.h>
#include <cuda_fp16.h>
#include <math.h>
#include <stdint.h>

#define B_ 16
#define C_ 512
#define HW_ 4096
#define HEADS_ 8
#define HK_ 64

// ------------------------- scratch (device globals) -------------------------
__device__ float g_q[B_ * C_ * HW_];
__device__ float g_k[B_ * C_ * HW_];
__device__ float g_v[B_ * C_ * HW_];
__device__ float g_ctx[B_ * HEADS_ * HK_ * HK_];
__device__ __half g_xt[(size_t)B_ * HW_ * C_];   // x transposed fp16; reused as AVt
__device__ __half g_wc[1536 * 512];              // Wq|Wk|Wv fp16
__device__ __half g_wr[512 * 512];               // Wr fp16
__device__ float g_bcat[1536];

// ------------------------- PTX helpers -------------------------
__device__ __forceinline__ uint32_t smem_u32(const void* p) {
    return (uint32_t)__cvta_generic_to_shared(p);
}
__device__ __forceinline__ void cp16(uint32_t dst, const void* src) {
    asm volatile("cp.async.cg.shared.global [%0], [%1], 16;\n" :: "r"(dst), "l"(src));
}
__device__ __forceinline__ void cp_commit() {
    asm volatile("cp.async.commit_group;\n" ::: "memory");
}
template <int N>
__device__ __forceinline__ void cp_wait() {
    asm volatile("cp.async.wait_group %0;\n" :: "n"(N) : "memory");
}
__device__ __forceinline__ uint32_t sw128(uint32_t off) {
    return off ^ ((off >> 3) & 0x70);
}
__device__ __forceinline__ void ldsm4(uint32_t& r0, uint32_t& r1, uint32_t& r2,
                                      uint32_t& r3, uint32_t addr) {
    asm volatile("ldmatrix.sync.aligned.m8n8.x4.shared.b16 {%0,%1,%2,%3}, [%4];"
                 : "=r"(r0), "=r"(r1), "=r"(r2), "=r"(r3) : "r"(addr));
}
__device__ __forceinline__ void mma16816(float* c, uint32_t a0, uint32_t a1,
                                         uint32_t a2, uint32_t a3,
                                         uint32_t b0, uint32_t b1) {
    asm volatile(
        "mma.sync.aligned.m16n8k16.row.col.f32.f16.f16.f32 "
        "{%0,%1,%2,%3}, {%4,%5,%6,%7}, {%8,%9}, {%0,%1,%2,%3};"
        : "+f"(c[0]), "+f"(c[1]), "+f"(c[2]), "+f"(c[3])
        : "r"(a0), "r"(a1), "r"(a2), "r"(a3), "r"(b0), "r"(b1));
}

// ------------------------- prepass: weight convert/concat -------------------------
__global__ void __launch_bounds__(256) weight_prep(
    const float* __restrict__ Wq, const float* __restrict__ bq,
    const float* __restrict__ Wk, const float* __restrict__ bk,
    const float* __restrict__ Wv, const float* __restrict__ bv,
    const float* __restrict__ Wr)
{
    const int idx = blockIdx.x * 256 + threadIdx.x;   // < 2048*512
    const int m = idx >> 9;
    const int kk = idx & 511;
    if (m < 1536) {
        const float* src = (m < 512) ? Wq : (m < 1024) ? Wk : Wv;
        g_wc[idx] = __float2half(src[(size_t)(m & 511) * 512 + kk]);
    } else {
        g_wr[(size_t)(m - 1536) * 512 + kk] =
            __float2half(Wr[(size_t)(m - 1536) * 512 + kk]);
    }
    if (idx < 1536)
        g_bcat[idx] = (idx < 512) ? bq[idx] : (idx < 1024) ? bk[idx - 512] : bv[idx - 1024];
}

// ------------------------- prepass: transpose + convert x -------------------------
// X [b][c][l] fp32  ->  Xt [b][l][c] fp16
__global__ void __launch_bounds__(256) transpose_cvt(const float* __restrict__ X)
{
    __shared__ float t[32][33];
    const int l0 = blockIdx.x * 32;
    const int c0 = blockIdx.y * 32;
    const int b  = blockIdx.z;
    const int tx = threadIdx.x, ty = threadIdx.y;
    #pragma unroll
    for (int j = 0; j < 4; j++)
        t[ty + j * 8][tx] = X[((size_t)b * C_ + c0 + ty + j * 8) * HW_ + l0 + tx];
    __syncthreads();
    #pragma unroll
    for (int j = 0; j < 4; j++) {
        size_t o = ((size_t)b * HW_ + l0 + ty + j * 8) * C_ + c0 + tx;
        g_xt[o] = __float2half(t[tx][ty + j * 8]);
    }
}

// ------------------------- HMMA fp16 GEMM -------------------------
// D[m][n] = sum_k A[m][k] * B[n][k] + bias[m]   (A,B fp16 K-major, fp32 accum)
// CTA tile 128x128, 8 warps (2m x 4n), each warp 64x32. K chunks of 64, dbl-buf.
#define GEMM_SMEM_TOTAL 65536

__global__ void __launch_bounds__(256) gemm_mma(
    const __half* __restrict__ A, const __half* __restrict__ Bmat,
    const float* __restrict__ bias,
    float* o0, float* o1, float* o2)
{
    extern __shared__ char smem[];
    const uint32_t sbase = smem_u32(smem);
    const int tid  = threadIdx.x;
    const int wid  = tid >> 5;
    const int lane = tid & 31;
    const int wm = wid >> 2;          // 0..1  (64-row half)
    const int wn = wid & 3;           // 0..3  (32-col quarter)
    const int n0  = blockIdx.x * 128;
    const int Mg0 = blockIdx.y * 128;
    const int b   = blockIdx.z;
    const size_t bB = (size_t)b * HW_;

    // per-lane ldmatrix address components
    const int rowA  = lane & 15;
    const int kbA   = (lane >> 4) * 16;               // bytes
    const int nrowB = (lane & 7) + (lane >> 4) * 8;
    const int kbB   = ((lane >> 3) & 1) * 16;         // bytes

    auto load_chunk = [&](int chunk, int buf) {
        const uint32_t Ab = sbase + buf * 32768;
        const uint32_t Bb = Ab + 16384;
        const int kc = chunk * 64;
        #pragma unroll
        for (int it = 0; it < 4; it++) {       // A: 128 rows x 128B
            int idx = it * 256 + tid;
            int row = idx >> 3, cb = idx & 7;
            cp16(Ab + sw128((uint32_t)(row * 128 + cb * 16)),
                 A + (size_t)(Mg0 + row) * 512 + kc + cb * 8);
        }
        #pragma unroll
        for (int it = 0; it < 4; it++) {       // B: 128 rows x 128B
            int idx = it * 256 + tid;
            int row = idx >> 3, cb = idx & 7;
            cp16(Bb + sw128((uint32_t)(row * 128 + cb * 16)),
                 Bmat + (bB + n0 + row) * 512 + kc + cb * 8);
        }
        cp_commit();
    };

    float acc[4][4][4];
    #pragma unroll
    for (int i = 0; i < 4; i++)
        #pragma unroll
        for (int j = 0; j < 4; j++)
            #pragma unroll
            for (int r = 0; r < 4; r++) acc[i][j][r] = 0.f;

    load_chunk(0, 0);

    for (int i = 0; i < 8; i++) {
        if (i + 1 < 8) { load_chunk(i + 1, (i + 1) & 1); cp_wait<1>(); }
        else            cp_wait<0>();
        __syncthreads();

        const uint32_t Ab = sbase + (i & 1) * 32768;
        const uint32_t Bb = Ab + 16384;
        #pragma unroll
        for (int ks = 0; ks < 4; ks++) {
            uint32_t af[4][4];
            #pragma unroll
            for (int mi = 0; mi < 4; mi++) {
                uint32_t off = (uint32_t)((wm * 64 + mi * 16 + rowA) * 128 + ks * 32 + kbA);
                ldsm4(af[mi][0], af[mi][1], af[mi][2], af[mi][3], Ab + sw128(off));
            }
            uint32_t bf[8];
            #pragma unroll
            for (int j = 0; j < 2; j++) {
                uint32_t off = (uint32_t)((wn * 32 + j * 16 + nrowB) * 128 + ks * 32 + kbB);
                ldsm4(bf[j * 4 + 0], bf[j * 4 + 1], bf[j * 4 + 2], bf[j * 4 + 3],
                      Bb + sw128(off));
            }
            #pragma unroll
            for (int mi = 0; mi < 4; mi++)
                #pragma unroll
                for (int ni = 0; ni < 4; ni++)
                    mma16816(acc[mi][ni], af[mi][0], af[mi][1], af[mi][2], af[mi][3],
                             bf[2 * ni], bf[2 * ni + 1]);
        }
        __syncthreads();
    }

    // epilogue: direct stores (d frag: c0,c1 row=lane/4, c2,c3 row=lane/4+8)
    const int sel = blockIdx.y >> 2;
    float* outp = (sel == 0) ? o0 : (sel == 1) ? o1 : o2;
    const int mloc0 = (blockIdx.y & 3) * 128 + wm * 64;
    const int ncta0 = n0 + wn * 32 + 2 * (lane & 3);
    #pragma unroll
    for (int mi = 0; mi < 4; mi++) {
        #pragma unroll
        for (int pair = 0; pair < 2; pair++) {
            const int mloc = mloc0 + mi * 16 + (lane >> 2) + pair * 8;
            const float bv = bias[Mg0 + wm * 64 + mi * 16 + (lane >> 2) + pair * 8];
            float* rowp = outp + ((size_t)b * 512 + mloc) * HW_;
            #pragma unroll
            for (int ni = 0; ni < 4; ni++) {
                float2 v;
                v.x = acc[mi][ni][pair * 2 + 0] + bv;
                v.y = acc[mi][ni][pair * 2 + 1] + bv;
                *(float2*)(rowp + ncta0 + ni * 8) = v;
            }
        }
    }
}

// ------------------------- softmax over spatial axis -------------------------
__global__ void __launch_bounds__(256) softmax_spatial(float* __restrict__ data)
{
    __shared__ float buf[HW_];
    __shared__ float red[8];
    __shared__ float bcast;
    float* p = data + (size_t)blockIdx.x * HW_;
    const int tid = threadIdx.x;

    float mx = -1e30f;
    #pragma unroll
    for (int r = 0; r < 4; r++) {
        int idx = (tid << 2) + r * 1024;
        float4 v = *(const float4*)(p + idx);
        *(float4*)&buf[idx] = v;
        mx = fmaxf(mx, fmaxf(fmaxf(v.x, v.y), fmaxf(v.z, v.w)));
    }
    #pragma unroll
    for (int o = 16; o > 0; o >>= 1) mx = fmaxf(mx, __shfl_xor_sync(~0u, mx, o));
    if ((tid & 31) == 0) red[tid >> 5] = mx;
    __syncthreads();
    if (tid == 0) {
        float m = red[0];
        #pragma unroll
        for (int i = 1; i < 8; i++) m = fmaxf(m, red[i]);
        bcast = m;
    }
    __syncthreads();
    mx = bcast;

    float s = 0.f;
    #pragma unroll
    for (int r = 0; r < 4; r++) {
        int idx = (tid << 2) + r * 1024;
        float4 v = *(float4*)&buf[idx];
        v.x = expf(v.x - mx); v.y = expf(v.y - mx);
        v.z = expf(v.z - mx); v.w = expf(v.w - mx);
        *(float4*)&buf[idx] = v;
        s += v.x + v.y + v.z + v.w;
    }
    #pragma unroll
    for (int o = 16; o > 0; o >>= 1) s += __shfl_xor_sync(~0u, s, o);
    if ((tid & 31) == 0) red[tid >> 5] = s;
    __syncthreads();
    if (tid == 0) {
        float m = 0.f;
        #pragma unroll
        for (int i = 0; i < 8; i++) m += red[i];
        bcast = 1.0f / m;
    }
    __syncthreads();
    const float inv = bcast;
    #pragma unroll
    for (int r = 0; r < 4; r++) {
        int idx = (tid << 2) + r * 1024;
        float4 v = *(float4*)&buf[idx];
        v.x *= inv; v.y *= inv; v.z *= inv; v.w *= inv;
        *(float4*)(p + idx) = v;
    }
}

// ------------------------- softmax over 64-channel axis (Q) -------------------------
__global__ void __launch_bounds__(256) softmax_channel(float* __restrict__ q)
{
    const size_t t = (size_t)blockIdx.x * 256 + threadIdx.x;
    const int l  = (int)(t & (HW_ - 1));
    const int bh = (int)(t >> 12);
    float* base = q + (size_t)bh * HK_ * HW_ + l;

    float r[64];
    float mx = -1e30f;
    #pragma unroll
    for (int k = 0; k < 64; k++) { r[k] = base[(size_t)k * HW_]; mx = fmaxf(mx, r[k]); }
    float s = 0.f;
    #pragma unroll
    for (int k = 0; k < 64; k++) { r[k] = expf(r[k] - mx); s += r[k]; }
    const float inv = 1.0f / s;
    #pragma unroll
    for (int k = 0; k < 64; k++) base[(size_t)k * HW_] = r[k] * inv;
}

// ------------------------- ctx[b,h,k,v] = sum_l K V -------------------------
__global__ void __launch_bounds__(256) ctx_gemm(
    const float* __restrict__ K, const float* __restrict__ V,
    float* __restrict__ Cout)
{
    __shared__ float Ks[64][33];
    __shared__ float Vs[64][33];
    const int bh = blockIdx.x;
    const float* Kp = K + (size_t)bh * HK_ * HW_;
    const float* Vp = V + (size_t)bh * HK_ * HW_;
    const int tid = threadIdx.x;
    const int tx = tid & 15, ty = tid >> 4;

    float acc[4][4] = {};
    for (int l0 = 0; l0 < HW_; l0 += 32) {
        #pragma unroll
        for (int rp = 0; rp < 2; rp++) {
            int idx = tid + rp * 256;
            int row = idx >> 3;
            int ls  = (idx & 7) << 2;
            float4 k4 = *(const float4*)(Kp + (size_t)row * HW_ + l0 + ls);
            Ks[row][ls + 0] = k4.x; Ks[row][ls + 1] = k4.y;
            Ks[row][ls + 2] = k4.z; Ks[row][ls + 3] = k4.w;
            float4 v4 = *(const float4*)(Vp + (size_t)row * HW_ + l0 + ls);
            Vs[row][ls + 0] = v4.x; Vs[row][ls + 1] = v4.y;
            Vs[row][ls + 2] = v4.z; Vs[row][ls + 3] = v4.w;
        }
        __syncthreads();
        #pragma unroll
        for (int ll = 0; ll < 32; ll++) {
            float a[4], c[4];
            #pragma unroll
            for (int i = 0; i < 4; i++) { a[i] = Ks[(ty << 2) + i][ll]; c[i] = Vs[(tx << 2) + i][ll]; }
            #pragma unroll
            for (int i = 0; i < 4; i++)
                #pragma unroll
                for (int j = 0; j < 4; j++)
                    acc[i][j] += a[i] * c[j];
        }
        __syncthreads();
    }
    float* Cp = Cout + (size_t)bh * HK_ * HK_;
    #pragma unroll
    for (int i = 0; i < 4; i++) {
        float4 o4 = make_float4(acc[i][0], acc[i][1], acc[i][2], acc[i][3]);
        *(float4*)(Cp + (size_t)((ty << 2) + i) * 64 + (tx << 2)) = o4;
    }
}

// ------------------------- av + transposed fp16 output -------------------------
// av[b,h,v,l] = sum_k ctx[b,h,k,v] q[b,h,k,l]; writes AVt[b][l][h*64+v] fp16
__global__ void __launch_bounds__(256) av_gemm(
    const float* __restrict__ Cin, const float* __restrict__ Q)
{
    __shared__ float Cs[64][64];
    __shared__ float Qs[16][64];
    const int bh = blockIdx.y;
    const int n0 = blockIdx.x * 64;
    const float* Cp = Cin + (size_t)bh * HK_ * HK_;
    const float* Qp = Q   + (size_t)bh * HK_ * HW_;
    const int tid = threadIdx.x;
    const int tx = tid & 15, ty = tid >> 4;

    #pragma unroll
    for (int rr = 0; rr < 4; rr++)
        ((float4*)Cs)[tid + rr * 256] = ((const float4*)Cp)[tid + rr * 256];

    float acc[4][4] = {};
    for (int k0 = 0; k0 < 64; k0 += 16) {
        int ii = tid >> 4, ls = (tid & 15) << 2;
        *(float4*)&Qs[ii][ls] =
            *(const float4*)(Qp + (size_t)(k0 + ii) * HW_ + n0 + ls);
        __syncthreads();
        #pragma unroll
        for (int kk = 0; kk < 16; kk++) {
            float4 a4 = *(float4*)&Cs[k0 + kk][ty << 2];
            float4 b4 = *(float4*)&Qs[kk][tx << 2];
            float a[4] = {a4.x, a4.y, a4.z, a4.w};
            float c[4] = {b4.x, b4.y, b4.z, b4.w};
            #pragma unroll
            for (int i = 0; i < 4; i++)
                #pragma unroll
                for (int j = 0; j < 4; j++)
                    acc[i][j] += a[i] * c[j];
        }
        __syncthreads();
    }
    const int h = bh & 7;
    const int bb = bh >> 3;
    #pragma unroll
    for (int j = 0; j < 4; j++) {
        const int l = n0 + (tx << 2) + j;
        const size_t rowbase = ((size_t)bb * HW_ + l) * C_ + h * 64 + (ty << 2);
        #pragma unroll
        for (int i = 0; i < 4; i += 2) {
            __half2 p;
            p.x = __float2half(acc[i][j]);
            p.y = __float2half(acc[i + 1][j]);
            *(__half2*)(g_xt + rowbase + i) = p;
        }
    }
}

// ---------------------------------------------------------------------------
extern "C" void kernel_launch(void* const* d_in, const int* in_sizes, int n_in,
                              void* d_out, int out_size)
{
    const float* x  = (const float*)d_in[0];
    const float* Wk = (const float*)d_in[1];
    const float* bk = (const float*)d_in[2];
    const float* Wq = (const float*)d_in[3];
    const float* bq = (const float*)d_in[4];
    const float* Wv = (const float*)d_in[5];
    const float* bv = (const float*)d_in[6];
    const float* Wr = (const float*)d_in[7];
    const float* br = (const float*)d_in[8];
    float* out = (float*)d_out;

    float *q, *k, *v, *ctx, *bcat;
    __half *xt, *wc, *wr;
    cudaGetSymbolAddress((void**)&q,    g_q);
    cudaGetSymbolAddress((void**)&k,    g_k);
    cudaGetSymbolAddress((void**)&v,    g_v);
    cudaGetSymbolAddress((void**)&ctx,  g_ctx);
    cudaGetSymbolAddress((void**)&bcat, g_bcat);
    cudaGetSymbolAddress((void**)&xt,   g_xt);
    cudaGetSymbolAddress((void**)&wc,   g_wc);
    cudaGetSymbolAddress((void**)&wr,   g_wr);

    cudaFuncSetAttribute(gemm_mma, cudaFuncAttributeMaxDynamicSharedMemorySize,
                         GEMM_SMEM_TOTAL);

    weight_prep<<<4096, 256>>>(Wq, bq, Wk, bk, Wv, bv, Wr);
    transpose_cvt<<<dim3(HW_ / 32, C_ / 32, B_), dim3(32, 8)>>>(x);

    // QKV projection: M=1536 (q|k|v), N=4096 per batch
    gemm_mma<<<dim3(32, 12, B_), 256, GEMM_SMEM_TOTAL>>>(wc, xt, bcat, q, k, v);

    softmax_spatial<<<B_ * C_, 256>>>(k);
    softmax_channel<<<(B_ * HEADS_ * HW_) / 256, 256>>>(q);

    ctx_gemm<<<B_ * HEADS_, 256>>>(k, v, ctx);
    av_gemm<<<dim3(HW_ / 64, B_ * HEADS_), 256>>>(ctx, q);   // writes AVt into g_xt

    // output projection: M=512
    gemm_mma<<<dim3(32, 4, B_), 256, GEMM_SMEM_TOTAL>>>(wr, xt, br, out, out, out);
}

// round 4
// speedup vs baseline: 7.3068x; 1.7074x over previous
#include <cuda_runtime.h>
#include <cuda_fp16.h>
#include <math.h>
#include <stdint.h>

#define B_ 16
#define C_ 512
#define HW_ 4096
#define HEADS_ 8
#define HK_ 64

// ------------------------- scratch (device globals) -------------------------
__device__ __half g_xt[(size_t)B_ * HW_ * C_];   // x transposed fp16; reused as AVt
__device__ __half g_qh[(size_t)B_ * C_ * HW_];   // raw q fp16 [b][c][l]
__device__ __half g_kh[(size_t)B_ * C_ * HW_];   // k fp16 (softmaxed in place)
__device__ __half g_vh[(size_t)B_ * C_ * HW_];   // v fp16
__device__ __half g_qt[(size_t)B_ * HW_ * C_];   // softmaxed q transposed [bh][l][64]
__device__ __half g_ctxh[B_ * HEADS_ * HK_ * HK_]; // ctxT [bh][v][k]
__device__ __half g_wc[1536 * 512];              // Wq|Wk|Wv fp16
__device__ __half g_wr[512 * 512];               // Wr fp16
__device__ float g_bcat[1536];

// ------------------------- PTX helpers -------------------------
__device__ __forceinline__ uint32_t smem_u32(const void* p) {
    return (uint32_t)__cvta_generic_to_shared(p);
}
__device__ __forceinline__ void cp16(uint32_t dst, const void* src) {
    asm volatile("cp.async.cg.shared.global [%0], [%1], 16;\n" :: "r"(dst), "l"(src));
}
__device__ __forceinline__ void cp_commit() {
    asm volatile("cp.async.commit_group;\n" ::: "memory");
}
template <int N>
__device__ __forceinline__ void cp_wait() {
    asm volatile("cp.async.wait_group %0;\n" :: "n"(N) : "memory");
}
__device__ __forceinline__ uint32_t sw128(uint32_t off) {
    return off ^ ((off >> 3) & 0x70);
}
__device__ __forceinline__ void ldsm4(uint32_t& r0, uint32_t& r1, uint32_t& r2,
                                      uint32_t& r3, uint32_t addr) {
    asm volatile("ldmatrix.sync.aligned.m8n8.x4.shared.b16 {%0,%1,%2,%3}, [%4];"
                 : "=r"(r0), "=r"(r1), "=r"(r2), "=r"(r3) : "r"(addr));
}
__device__ __forceinline__ void mma16816(float* c, uint32_t a0, uint32_t a1,
                                         uint32_t a2, uint32_t a3,
                                         uint32_t b0, uint32_t b1) {
    asm volatile(
        "mma.sync.aligned.m16n8k16.row.col.f32.f16.f16.f32 "
        "{%0,%1,%2,%3}, {%4,%5,%6,%7}, {%8,%9}, {%0,%1,%2,%3};"
        : "+f"(c[0]), "+f"(c[1]), "+f"(c[2]), "+f"(c[3])
        : "r"(a0), "r"(a1), "r"(a2), "r"(a3), "r"(b0), "r"(b1));
}

// ------------------------- prepass: weight convert/concat -------------------------
__global__ void __launch_bounds__(256) weight_prep(
    const float* __restrict__ Wq, const float* __restrict__ bq,
    const float* __restrict__ Wk, const float* __restrict__ bk,
    const float* __restrict__ Wv, const float* __restrict__ bv,
    const float* __restrict__ Wr)
{
    const int idx = blockIdx.x * 256 + threadIdx.x;   // < 2048*512
    const int m = idx >> 9;
    const int kk = idx & 511;
    if (m < 1536) {
        const float* src = (m < 512) ? Wq : (m < 1024) ? Wk : Wv;
        g_wc[idx] = __float2half(src[(size_t)(m & 511) * 512 + kk]);
    } else {
        g_wr[(size_t)(m - 1536) * 512 + kk] =
            __float2half(Wr[(size_t)(m - 1536) * 512 + kk]);
    }
    if (idx < 1536)
        g_bcat[idx] = (idx < 512) ? bq[idx] : (idx < 1024) ? bk[idx - 512] : bv[idx - 1024];
}

// ------------------------- prepass: transpose + convert x -------------------------
__global__ void __launch_bounds__(256) transpose_cvt(const float* __restrict__ X)
{
    __shared__ float t[32][33];
    const int l0 = blockIdx.x * 32;
    const int c0 = blockIdx.y * 32;
    const int b  = blockIdx.z;
    const int tx = threadIdx.x, ty = threadIdx.y;
    #pragma unroll
    for (int j = 0; j < 4; j++)
        t[ty + j * 8][tx] = X[((size_t)b * C_ + c0 + ty + j * 8) * HW_ + l0 + tx];
    __syncthreads();
    #pragma unroll
    for (int j = 0; j < 4; j++) {
        size_t o = ((size_t)b * HW_ + l0 + ty + j * 8) * C_ + c0 + tx;
        g_xt[o] = __float2half(t[tx][ty + j * 8]);
    }
}

// ------------------------- HMMA fp16 GEMM (projections) -------------------------
// D[m][n] = sum_k A[m][k]*B[n][k] + bias[m]; CTA 128x128, K chunks 64, dbl-buf.
#define GEMM_SMEM_TOTAL 65536

template <bool OUT_HALF>
__global__ void __launch_bounds__(256) gemm_mma(
    const __half* __restrict__ A, const __half* __restrict__ Bmat,
    const float* __restrict__ bias,
    void* o0v, void* o1v, void* o2v)
{
    extern __shared__ char smem[];
    const uint32_t sbase = smem_u32(smem);
    const int tid  = threadIdx.x;
    const int wid  = tid >> 5;
    const int lane = tid & 31;
    const int wm = wid >> 2;
    const int wn = wid & 3;
    const int n0  = blockIdx.x * 128;
    const int Mg0 = blockIdx.y * 128;
    const int b   = blockIdx.z;
    const size_t bB = (size_t)b * HW_;

    const int rowA  = lane & 15;
    const int kbA   = (lane >> 4) * 16;
    const int nrowB = (lane & 7) + (lane >> 4) * 8;
    const int kbB   = ((lane >> 3) & 1) * 16;

    auto load_chunk = [&](int chunk, int buf) {
        const uint32_t Ab = sbase + buf * 32768;
        const uint32_t Bb = Ab + 16384;
        const int kc = chunk * 64;
        #pragma unroll
        for (int it = 0; it < 4; it++) {
            int idx = it * 256 + tid;
            int row = idx >> 3, cb = idx & 7;
            cp16(Ab + sw128((uint32_t)(row * 128 + cb * 16)),
                 A + (size_t)(Mg0 + row) * 512 + kc + cb * 8);
        }
        #pragma unroll
        for (int it = 0; it < 4; it++) {
            int idx = it * 256 + tid;
            int row = idx >> 3, cb = idx & 7;
            cp16(Bb + sw128((uint32_t)(row * 128 + cb * 16)),
                 Bmat + (bB + n0 + row) * 512 + kc + cb * 8);
        }
        cp_commit();
    };

    float acc[4][4][4];
    #pragma unroll
    for (int i = 0; i < 4; i++)
        #pragma unroll
        for (int j = 0; j < 4; j++)
            #pragma unroll
            for (int r = 0; r < 4; r++) acc[i][j][r] = 0.f;

    load_chunk(0, 0);

    for (int i = 0; i < 8; i++) {
        if (i + 1 < 8) { load_chunk(i + 1, (i + 1) & 1); cp_wait<1>(); }
        else            cp_wait<0>();
        __syncthreads();

        const uint32_t Ab = sbase + (i & 1) * 32768;
        const uint32_t Bb = Ab + 16384;
        #pragma unroll
        for (int ks = 0; ks < 4; ks++) {
            uint32_t af[4][4];
            #pragma unroll
            for (int mi = 0; mi < 4; mi++) {
                uint32_t off = (uint32_t)((wm * 64 + mi * 16 + rowA) * 128 + ks * 32 + kbA);
                ldsm4(af[mi][0], af[mi][1], af[mi][2], af[mi][3], Ab + sw128(off));
            }
            uint32_t bf[8];
            #pragma unroll
            for (int j = 0; j < 2; j++) {
                uint32_t off = (uint32_t)((wn * 32 + j * 16 + nrowB) * 128 + ks * 32 + kbB);
                ldsm4(bf[j * 4 + 0], bf[j * 4 + 1], bf[j * 4 + 2], bf[j * 4 + 3],
                      Bb + sw128(off));
            }
            #pragma unroll
            for (int mi = 0; mi < 4; mi++)
                #pragma unroll
                for (int ni = 0; ni < 4; ni++)
                    mma16816(acc[mi][ni], af[mi][0], af[mi][1], af[mi][2], af[mi][3],
                             bf[2 * ni], bf[2 * ni + 1]);
        }
        __syncthreads();
    }

    const int sel = blockIdx.y >> 2;
    const int mloc_cta = (blockIdx.y & 3) * 128;
    const int ncta0 = n0 + wn * 32 + 2 * (lane & 3);
    #pragma unroll
    for (int mi = 0; mi < 4; mi++) {
        #pragma unroll
        for (int pair = 0; pair < 2; pair++) {
            const int msub = wm * 64 + mi * 16 + (lane >> 2) + pair * 8;
            const int mloc = mloc_cta + msub;
            const float bv = bias[Mg0 + msub];
            if (OUT_HALF) {
                __half* outp = (__half*)((sel == 0) ? o0v : (sel == 1) ? o1v : o2v);
                __half* rowp = outp + ((size_t)b * 512 + mloc) * HW_;
                #pragma unroll
                for (int ni = 0; ni < 4; ni++) {
                    __half2 v = __floats2half2_rn(acc[mi][ni][pair * 2 + 0] + bv,
                                                  acc[mi][ni][pair * 2 + 1] + bv);
                    *(__half2*)(rowp + ncta0 + ni * 8) = v;
                }
            } else {
                float* outp = (float*)((sel == 0) ? o0v : (sel == 1) ? o1v : o2v);
                float* rowp = outp + ((size_t)b * 512 + mloc) * HW_;
                #pragma unroll
                for (int ni = 0; ni < 4; ni++) {
                    float2 v;
                    v.x = acc[mi][ni][pair * 2 + 0] + bv;
                    v.y = acc[mi][ni][pair * 2 + 1] + bv;
                    *(float2*)(rowp + ncta0 + ni * 8) = v;
                }
            }
        }
    }
}

// ------------------------- softmax over spatial axis, fp16 in/out -------------------------
__global__ void __launch_bounds__(256) softmax_spatial_h(__half* __restrict__ data)
{
    __shared__ float buf[HW_];
    __shared__ float red[8];
    __shared__ float bcast;
    __half2* p2 = (__half2*)(data + (size_t)blockIdx.x * HW_);
    const int tid = threadIdx.x;

    float mx = -1e30f;
    #pragma unroll
    for (int r = 0; r < 8; r++) {
        int idx = tid + r * 256;
        float2 f = __half22float2(p2[idx]);
        buf[2 * idx] = f.x; buf[2 * idx + 1] = f.y;
        mx = fmaxf(mx, fmaxf(f.x, f.y));
    }
    #pragma unroll
    for (int o = 16; o > 0; o >>= 1) mx = fmaxf(mx, __shfl_xor_sync(~0u, mx, o));
    if ((tid & 31) == 0) red[tid >> 5] = mx;
    __syncthreads();
    if (tid == 0) {
        float m = red[0];
        #pragma unroll
        for (int i = 1; i < 8; i++) m = fmaxf(m, red[i]);
        bcast = m;
    }
    __syncthreads();
    mx = bcast;

    float s = 0.f;
    #pragma unroll
    for (int r = 0; r < 8; r++) {
        int idx = tid + r * 256;
        float a = expf(buf[2 * idx] - mx);
        float bvv = expf(buf[2 * idx + 1] - mx);
        buf[2 * idx] = a; buf[2 * idx + 1] = bvv;
        s += a + bvv;
    }
    #pragma unroll
    for (int o = 16; o > 0; o >>= 1) s += __shfl_xor_sync(~0u, s, o);
    if ((tid & 31) == 0) red[tid >> 5] = s;
    __syncthreads();
    if (tid == 0) {
        float m = 0.f;
        #pragma unroll
        for (int i = 0; i < 8; i++) m += red[i];
        bcast = 1.0f / m;
    }
    __syncthreads();
    const float inv = bcast;
    #pragma unroll
    for (int r = 0; r < 8; r++) {
        int idx = tid + r * 256;
        p2[idx] = __floats2half2_rn(buf[2 * idx] * inv, buf[2 * idx + 1] * inv);
    }
}

// ------------------------- softmax over 64-channel axis + transpose -------------------------
// q [bh][k=64][l] fp16 -> qt [bh][l][k=64] fp16 (softmax over k)
__global__ void __launch_bounds__(256) softmax_channel_t(
    const __half* __restrict__ q, __half* __restrict__ qt)
{
    const size_t t = (size_t)blockIdx.x * 256 + threadIdx.x;
    const int l  = (int)(t & (HW_ - 1));
    const int bh = (int)(t >> 12);
    const __half* base = q + (size_t)bh * HK_ * HW_ + l;

    float r[64];
    float mx = -1e30f;
    #pragma unroll
    for (int k = 0; k < 64; k++) {
        r[k] = __half2float(base[(size_t)k * HW_]);
        mx = fmaxf(mx, r[k]);
    }
    float s = 0.f;
    #pragma unroll
    for (int k = 0; k < 64; k++) { r[k] = expf(r[k] - mx); s += r[k]; }
    const float inv = 1.0f / s;

    __half2 h2[32];
    #pragma unroll
    for (int k = 0; k < 32; k++)
        h2[k] = __floats2half2_rn(r[2 * k] * inv, r[2 * k + 1] * inv);
    uint4* dst = (uint4*)(qt + ((size_t)bh * HW_ + l) * 64);
    uint4* srcp = (uint4*)h2;
    #pragma unroll
    for (int i = 0; i < 8; i++) dst[i] = srcp[i];
}

// ------------------------- ctx HMMA: ctxT[bh][v][k] = sum_l K[k,l] V[v,l] -------------------------
#define CTX_SMEM 32768
__global__ void __launch_bounds__(256) ctx_mma(
    const __half* __restrict__ K, const __half* __restrict__ V,
    __half* __restrict__ CtxT)
{
    extern __shared__ char smem[];
    const uint32_t sbase = smem_u32(smem);
    const int bh = blockIdx.x;
    const int tid = threadIdx.x;
    const int wid = tid >> 5;
    const int lane = tid & 31;
    const int wm = wid >> 1;    // 0..3 (16-row m tile)
    const int wn = wid & 1;     // 0..1 (32-col n tile)
    const __half* Kp = K + (size_t)bh * HK_ * HW_;
    const __half* Vp = V + (size_t)bh * HK_ * HW_;

    const int rowA  = lane & 15;
    const int kbA   = (lane >> 4) * 16;
    const int nrowB = (lane & 7) + (lane >> 4) * 8;
    const int kbB   = ((lane >> 3) & 1) * 16;

    auto load_chunk = [&](int chunk, int buf) {
        const uint32_t Ab = sbase + buf * 16384;
        const uint32_t Bb = Ab + 8192;
        const int lc = chunk * 64;
        #pragma unroll
        for (int it = 0; it < 2; it++) {
            int idx = it * 256 + tid;        // 0..511
            int row = idx >> 3, cb = idx & 7;
            cp16(Ab + sw128((uint32_t)(row * 128 + cb * 16)),
                 Kp + (size_t)row * HW_ + lc + cb * 8);
            cp16(Bb + sw128((uint32_t)(row * 128 + cb * 16)),
                 Vp + (size_t)row * HW_ + lc + cb * 8);
        }
        cp_commit();
    };

    float acc[4][4];
    #pragma unroll
    for (int i = 0; i < 4; i++)
        #pragma unroll
        for (int r = 0; r < 4; r++) acc[i][r] = 0.f;

    load_chunk(0, 0);
    for (int i = 0; i < 64; i++) {
        if (i + 1 < 64) { load_chunk(i + 1, (i + 1) & 1); cp_wait<1>(); }
        else             cp_wait<0>();
        __syncthreads();
        const uint32_t Ab = sbase + (i & 1) * 16384;
        const uint32_t Bb = Ab + 8192;
        #pragma unroll
        for (int ks = 0; ks < 4; ks++) {
            uint32_t a0, a1, a2, a3;
            ldsm4(a0, a1, a2, a3,
                  Ab + sw128((uint32_t)((wm * 16 + rowA) * 128 + ks * 32 + kbA)));
            uint32_t bf[8];
            #pragma unroll
            for (int j = 0; j < 2; j++)
                ldsm4(bf[j * 4 + 0], bf[j * 4 + 1], bf[j * 4 + 2], bf[j * 4 + 3],
                      Bb + sw128((uint32_t)((wn * 32 + j * 16 + nrowB) * 128 + ks * 32 + kbB)));
            #pragma unroll
            for (int ni = 0; ni < 4; ni++)
                mma16816(acc[ni], a0, a1, a2, a3, bf[2 * ni], bf[2 * ni + 1]);
        }
        __syncthreads();
    }

    // stage fp32 ctx[k][v] in smem, then write transposed fp16
    float* ctxs = (float*)smem;   // [64][65]
    __syncthreads();
    {
        const int r0 = wm * 16 + (lane >> 2);
        #pragma unroll
        for (int ni = 0; ni < 4; ni++) {
            const int col = wn * 32 + ni * 8 + 2 * (lane & 3);
            ctxs[r0 * 65 + col]           = acc[ni][0];
            ctxs[r0 * 65 + col + 1]       = acc[ni][1];
            ctxs[(r0 + 8) * 65 + col]     = acc[ni][2];
            ctxs[(r0 + 8) * 65 + col + 1] = acc[ni][3];
        }
    }
    __syncthreads();
    {
        const int v = tid >> 2;
        const int k0 = (tid & 3) * 16;
        __half* dst = CtxT + (size_t)bh * 4096 + v * 64 + k0;
        #pragma unroll
        for (int j = 0; j < 8; j++) {
            *(__half2*)(dst + 2 * j) =
                __floats2half2_rn(ctxs[(k0 + 2 * j) * 65 + v],
                                  ctxs[(k0 + 2 * j + 1) * 65 + v]);
        }
    }
}

// ------------------------- av HMMA: AVt[b][l][h*64+v] = sum_k ctxT[v,k] qt[l,k] -------------------------
#define AV_SMEM (8192 + 32768)
__global__ void __launch_bounds__(256) av_mma(
    const __half* __restrict__ CtxT, const __half* __restrict__ Qt,
    __half* __restrict__ AVt)
{
    extern __shared__ char smem[];
    const uint32_t sbase = smem_u32(smem);
    const int bh = blockIdx.y;
    const int l0 = blockIdx.x * 256;
    const int tid = threadIdx.x;
    const int wid = tid >> 5;
    const int lane = tid & 31;
    const int wm = wid >> 2;   // 0..1 (32-row m)
    const int wn = wid & 3;    // 0..3 (64-col n)

    const int rowA  = lane & 15;
    const int kbA   = (lane >> 4) * 16;
    const int nrowB = (lane & 7) + (lane >> 4) * 8;
    const int kbB   = ((lane >> 3) & 1) * 16;

    const uint32_t Ab = sbase;          // ctxT: 64 rows x 128B
    const uint32_t Bb = sbase + 8192;   // qt tile: 256 rows x 128B

    // load ctxT (512 cp16) + qt tile (2048 cp16)
    #pragma unroll
    for (int it = 0; it < 2; it++) {
        int idx = it * 256 + tid;
        int row = idx >> 3, cb = idx & 7;
        cp16(Ab + sw128((uint32_t)(row * 128 + cb * 16)),
             CtxT + (size_t)bh * 4096 + row * 64 + cb * 8);
    }
    #pragma unroll
    for (int it = 0; it < 8; it++) {
        int idx = it * 256 + tid;
        int row = idx >> 3, cb = idx & 7;
        cp16(Bb + sw128((uint32_t)(row * 128 + cb * 16)),
             Qt + ((size_t)bh * HW_ + l0 + row) * 64 + cb * 8);
    }
    cp_commit();
    cp_wait<0>();
    __syncthreads();

    float acc[2][8][4];
    #pragma unroll
    for (int i = 0; i < 2; i++)
        #pragma unroll
        for (int j = 0; j < 8; j++)
            #pragma unroll
            for (int r = 0; r < 4; r++) acc[i][j][r] = 0.f;

    #pragma unroll
    for (int ks = 0; ks < 4; ks++) {
        uint32_t af[2][4];
        #pragma unroll
        for (int mi = 0; mi < 2; mi++)
            ldsm4(af[mi][0], af[mi][1], af[mi][2], af[mi][3],
                  Ab + sw128((uint32_t)((wm * 32 + mi * 16 + rowA) * 128 + ks * 32 + kbA)));
        uint32_t bf[4][4];
        #pragma unroll
        for (int j = 0; j < 4; j++)
            ldsm4(bf[j][0], bf[j][1], bf[j][2], bf[j][3],
                  Bb + sw128((uint32_t)((wn * 64 + j * 16 + nrowB) * 128 + ks * 32 + kbB)));
        #pragma unroll
        for (int mi = 0; mi < 2; mi++)
            #pragma unroll
            for (int ni = 0; ni < 8; ni++) {
                int j = ni >> 1, pr = (ni & 1) * 2;
                mma16816(acc[mi][ni], af[mi][0], af[mi][1], af[mi][2], af[mi][3],
                         bf[j][pr], bf[j][pr + 1]);
            }
    }
    __syncthreads();

    // stage transposed [l][v] fp16 in smem (reuse B region)
    __half* outs = (__half*)(smem + 8192);   // [256][64]
    #pragma unroll
    for (int mi = 0; mi < 2; mi++) {
        const int r0 = wm * 32 + mi * 16 + (lane >> 2);
        #pragma unroll
        for (int ni = 0; ni < 8; ni++) {
            const int n = wn * 64 + ni * 8 + 2 * (lane & 3);
            outs[n * 64 + r0]             = __float2half(acc[mi][ni][0]);
            outs[(n + 1) * 64 + r0]       = __float2half(acc[mi][ni][1]);
            outs[n * 64 + r0 + 8]         = __float2half(acc[mi][ni][2]);
            outs[(n + 1) * 64 + r0 + 8]   = __float2half(acc[mi][ni][3]);
        }
    }
    __syncthreads();

    const int b = bh >> 3;
    const int h = bh & 7;
    const __half2* src2 = (const __half2*)outs;
    #pragma unroll
    for (int it = 0; it < 32; it++) {
        int idx = it * 256 + tid;          // half2 index, 8192 total
        int row = idx >> 5;
        int c2  = idx & 31;
        *(__half2*)(AVt + ((size_t)b * HW_ + l0 + row) * 512 + h * 64 + c2 * 2) = src2[idx];
    }
}

// ---------------------------------------------------------------------------
extern "C" void kernel_launch(void* const* d_in, const int* in_sizes, int n_in,
                              void* d_out, int out_size)
{
    const float* x  = (const float*)d_in[0];
    const float* Wk = (const float*)d_in[1];
    const float* bk = (const float*)d_in[2];
    const float* Wq = (const float*)d_in[3];
    const float* bq = (const float*)d_in[4];
    const float* Wv = (const float*)d_in[5];
    const float* bv = (const float*)d_in[6];
    const float* Wr = (const float*)d_in[7];
    const float* br = (const float*)d_in[8];
    float* out = (float*)d_out;

    float *bcat;
    __half *xt, *qh, *kh, *vh, *qt, *ctxh, *wc, *wr;
    cudaGetSymbolAddress((void**)&bcat, g_bcat);
    cudaGetSymbolAddress((void**)&xt,   g_xt);
    cudaGetSymbolAddress((void**)&qh,   g_qh);
    cudaGetSymbolAddress((void**)&kh,   g_kh);
    cudaGetSymbolAddress((void**)&vh,   g_vh);
    cudaGetSymbolAddress((void**)&qt,   g_qt);
    cudaGetSymbolAddress((void**)&ctxh, g_ctxh);
    cudaGetSymbolAddress((void**)&wc,   g_wc);
    cudaGetSymbolAddress((void**)&wr,   g_wr);

    cudaFuncSetAttribute(gemm_mma<true>, cudaFuncAttributeMaxDynamicSharedMemorySize,
                         GEMM_SMEM_TOTAL);
    cudaFuncSetAttribute(gemm_mma<false>, cudaFuncAttributeMaxDynamicSharedMemorySize,
                         GEMM_SMEM_TOTAL);

    weight_prep<<<4096, 256>>>(Wq, bq, Wk, bk, Wv, bv, Wr);
    transpose_cvt<<<dim3(HW_ / 32, C_ / 32, B_), dim3(32, 8)>>>(x);

    // QKV projection -> fp16 q,k,v
    gemm_mma<true><<<dim3(32, 12, B_), 256, GEMM_SMEM_TOTAL>>>(wc, xt, bcat, qh, kh, vh);

    softmax_spatial_h<<<B_ * C_, 256>>>(kh);
    softmax_channel_t<<<(B_ * HEADS_ * HW_) / 256, 256>>>(qh, qt);

    ctx_mma<<<B_ * HEADS_, 256, CTX_SMEM>>>(kh, vh, ctxh);
    av_mma<<<dim3(HW_ / 256, B_ * HEADS_), 256, AV_SMEM>>>(ctxh, qt, xt);  // AVt into g_xt

    // output projection: fp32 out
    gemm_mma<false><<<dim3(32, 4, B_), 256, GEMM_SMEM_TOTAL>>>(wr, xt, br, out, out, out);
}